// round 10
// baseline (speedup 1.0000x reference)
#include <cuda_runtime.h>

#define HID 128
#define H   8
#define HD  16
#define NMAX 50000
#define EMAX 800000
#define SCAN_B 256

// packed f32x2 helpers (sm_100a)
#define PACK2(out, lo, hi) \
    asm("mov.b64 %0, {%1, %2};" : "=l"(out) : "r"(__float_as_uint(lo)), "r"(__float_as_uint(hi)))
#define UNPACK2(lo, hi, in) \
    { unsigned int _l, _h; \
      asm("mov.b64 {%0, %1}, %2;" : "=r"(_l), "=r"(_h) : "l"(in)); \
      lo = __uint_as_float(_l); hi = __uint_as_float(_h); }
#define FMA2(d, a, b) \
    asm("fma.rn.f32x2 %0, %1, %2, %0;" : "+l"(d) : "l"(a), "l"(b))

// ---------------- scratch (no allocations; statics are zero-initialized) ----------------
__device__ float g_weff_src[HID * H];
__device__ float g_weff_dst[HID * H];
__device__ float g_beff[2 * H];
__device__ float g_alpha_src[NMAX * H];
__device__ float g_alpha_dst[NMAX * H];
__device__ int   g_count[NMAX];          // zero at load; re-zeroed by k_scatter each call
__device__ int   g_offsets[NMAX + 1];
__device__ int   g_rank[EMAX];           // edge's arrival index within its dst segment
__device__ int   g_src_sorted[EMAX];
__device__ float g_agg[NMAX * HID];

// ---- k1: degree histogram (+rank capture), x4 vectorized + (block 0) weff fold ----
__global__ void k_count(const int* __restrict__ ei, int e, int n,
                        const float* __restrict__ node_w,
                        const float* __restrict__ node_b,
                        const float* __restrict__ att_w) {
    int idx = blockIdx.x * blockDim.x + threadIdx.x;
    int base = idx * 4;
    if (base + 3 < e) {
        int4 c4 = *(const int4*)(ei + e + base);
        int r0, r1, r2, r3;
        r0 = atomicAdd(&g_count[min(max(c4.x, 0), n - 1)], 1);
        r1 = atomicAdd(&g_count[min(max(c4.y, 0), n - 1)], 1);
        r2 = atomicAdd(&g_count[min(max(c4.z, 0), n - 1)], 1);
        r3 = atomicAdd(&g_count[min(max(c4.w, 0), n - 1)], 1);
        *(int4*)(g_rank + base) = make_int4(r0, r1, r2, r3);
    } else {
        for (int i = base; i < e; i++) {
            int c = min(max(ei[e + i], 0), n - 1);
            g_rank[i] = atomicAdd(&g_count[c], 1);
        }
    }
    if (blockIdx.x == 0) {
        int t = threadIdx.x;
        for (int p = t; p < HID * H; p += blockDim.x) {
            int k = p / H, h = p % H;
            float ss = 0.f, sd = 0.f;
            #pragma unroll
            for (int d = 0; d < HD; d++) {
                ss += node_w[k * (2 * HID) + h * (2 * HD) + d]      * att_w[h * (2 * HD) + d];
                sd += node_w[k * (2 * HID) + h * (2 * HD) + HD + d] * att_w[h * (2 * HD) + HD + d];
            }
            g_weff_src[k * H + h] = ss;
            g_weff_dst[k * H + h] = sd;
        }
        if (t < H) {
            float bs = 0.f, bd = 0.f;
            #pragma unroll
            for (int d = 0; d < HD; d++) {
                bs += node_b[t * (2 * HD) + d]      * att_w[t * (2 * HD) + d];
                bd += node_b[t * (2 * HD) + HD + d] * att_w[t * (2 * HD) + HD + d];
            }
            g_beff[t]     = bs;
            g_beff[H + t] = bd;
        }
    }
}

// ---- k2: blocks [0,nb): offsets scan (self-summed prefix); blocks [nb,..): alpha ----
__global__ void k_alpha_scan(const float* __restrict__ X, int n, int nb) {
    __shared__ float sw[16][HID];
    __shared__ int wsum[8];
    __shared__ int s_base;
    int tid = threadIdx.x, lane = tid & 31, wid = tid >> 5;

    if (blockIdx.x < nb) {
        // ---- scan block: base = sum of counts[0 .. blockIdx*256) ----
        int pend = blockIdx.x * SCAN_B;
        int sum = 0;
        for (int i = tid; i < pend; i += SCAN_B) sum += g_count[i];
        #pragma unroll
        for (int o = 16; o > 0; o >>= 1) sum += __shfl_xor_sync(0xffffffffu, sum, o);
        if (lane == 0) wsum[wid] = sum;
        __syncthreads();
        if (tid == 0) {
            int s = 0;
            #pragma unroll
            for (int k = 0; k < 8; k++) s += wsum[k];
            s_base = s;
        }
        __syncthreads();
        int bbase = s_base;
        __syncthreads();    // wsum reuse barrier

        int i = pend + tid;
        int v = (i < n) ? g_count[i] : 0;
        int x = v;
        #pragma unroll
        for (int o = 1; o < 32; o <<= 1) {
            int y = __shfl_up_sync(0xffffffffu, x, o);
            if (lane >= o) x += y;
        }
        if (lane == 31) wsum[wid] = x;
        __syncthreads();
        if (wid == 0 && lane < 8) {
            int s = wsum[lane];
            #pragma unroll
            for (int o = 1; o < 8; o <<= 1) {
                int y = __shfl_up_sync(0xffu, s, o);
                if (lane >= o) s += y;
            }
            wsum[lane] = s;
        }
        __syncthreads();
        int woff = (wid > 0) ? wsum[wid - 1] : 0;
        int incl = bbase + woff + x;
        if (i < n) g_offsets[i] = incl - v;
        if (blockIdx.x == nb - 1 && tid == SCAN_B - 1) g_offsets[n] = incl;
        return;
    }

    // ---- alpha block: warp-per-node, row read once ----
    for (int idx = tid; idx < 16 * HID; idx += blockDim.x) {
        int hh = idx >> 7, k = idx & 127;
        sw[hh][k] = (hh < 8) ? g_weff_src[k * H + hh] : g_weff_dst[k * H + (hh - 8)];
    }
    __syncthreads();
    int node = (blockIdx.x - nb) * 8 + wid;
    if (node >= n) return;
    float4 xv = ((const float4*)(X + (size_t)node * HID))[lane];
    float r[16];
    #pragma unroll
    for (int hh = 0; hh < 16; hh++) {
        float4 wv = *(const float4*)&sw[hh][lane * 4];
        r[hh] = xv.x * wv.x + xv.y * wv.y + xv.z * wv.z + xv.w * wv.w;
    }
    #pragma unroll
    for (int o = 16; o > 0; o >>= 1)
        #pragma unroll
        for (int hh = 0; hh < 16; hh++)
            r[hh] += __shfl_xor_sync(0xffffffffu, r[hh], o);
    if (lane == 0) {
        float4* ps = (float4*)(g_alpha_src + (size_t)node * H);
        ps[0] = make_float4(r[0] + g_beff[0], r[1] + g_beff[1], r[2] + g_beff[2], r[3] + g_beff[3]);
        ps[1] = make_float4(r[4] + g_beff[4], r[5] + g_beff[5], r[6] + g_beff[6], r[7] + g_beff[7]);
        float4* pd = (float4*)(g_alpha_dst + (size_t)node * H);
        pd[0] = make_float4(r[8]  + g_beff[8],  r[9]  + g_beff[9],  r[10] + g_beff[10], r[11] + g_beff[11]);
        pd[1] = make_float4(r[12] + g_beff[12], r[13] + g_beff[13], r[14] + g_beff[14], r[15] + g_beff[15]);
    }
}

// ---- k3: atomic-free permutation scatter, x4 vectorized; also zeroes g_count ----
__global__ void k_scatter(const int* __restrict__ ei, int e, int n) {
    int idx = blockIdx.x * blockDim.x + threadIdx.x;
    if (idx < n) g_count[idx] = 0;                 // reset for next graph replay
    int base = idx * 4;
    if (base + 3 < e) {
        int4 r4 = *(const int4*)(ei + base);
        int4 c4 = *(const int4*)(ei + e + base);
        int4 k4 = *(const int4*)(g_rank + base);
        int o0 = g_offsets[min(max(c4.x, 0), n - 1)];
        int o1 = g_offsets[min(max(c4.y, 0), n - 1)];
        int o2 = g_offsets[min(max(c4.z, 0), n - 1)];
        int o3 = g_offsets[min(max(c4.w, 0), n - 1)];
        g_src_sorted[o0 + k4.x] = min(max(r4.x, 0), n - 1);
        g_src_sorted[o1 + k4.y] = min(max(r4.y, 0), n - 1);
        g_src_sorted[o2 + k4.z] = min(max(r4.z, 0), n - 1);
        g_src_sorted[o3 + k4.w] = min(max(r4.w, 0), n - 1);
    } else {
        for (int i = base; i < e; i++) {
            int row = min(max(ei[i], 0), n - 1);
            int col = min(max(ei[e + i], 0), n - 1);
            g_src_sorted[g_offsets[col] + g_rank[i]] = row;
        }
    }
}

// ---- k4: fused scores + shift-free softmax + weighted gather (PROFILED pos 4) ----
__global__ void __launch_bounds__(256) k_agg(const float* __restrict__ X, int n) {
    __shared__ float sp[8][32][9];
    __shared__ int   ssrc[8][32];
    int w = threadIdx.x >> 5, lane = threadIdx.x & 31;
    int node = blockIdx.x * 8 + w;
    if (node >= n) return;
    int start = g_offsets[node];
    int end   = g_offsets[node + 1];

    const float4* bd4 = (const float4*)(g_alpha_dst + (size_t)node * H);
    float4 bd0 = bd4[0], bd1 = bd4[1];

    float den = 0.f;
    unsigned long long acc01 = 0ULL, acc23 = 0ULL;
    const int hsel = lane >> 2;

    for (int j0 = start; j0 < end; j0 += 32) {
        int j = j0 + lane;
        float p[8];
        int src = 0;
        if (j < end) {
            src = g_src_sorted[j];
            const float4* as4 = (const float4*)(g_alpha_src + (size_t)src * H);
            float4 a0 = as4[0], a1 = as4[1];
            float s[8];
            s[0] = a0.x + bd0.x; s[1] = a0.y + bd0.y;
            s[2] = a0.z + bd0.z; s[3] = a0.w + bd0.w;
            s[4] = a1.x + bd1.x; s[5] = a1.y + bd1.y;
            s[6] = a1.z + bd1.z; s[7] = a1.w + bd1.w;
            #pragma unroll
            for (int h = 0; h < 8; h++) {
                float v = (s[h] >= 0.f) ? s[h] : 0.2f * s[h];
                p[h] = __expf(v);
            }
        } else {
            #pragma unroll
            for (int h = 0; h < 8; h++) p[h] = 0.f;
        }
        #pragma unroll
        for (int h = 0; h < 8; h++) sp[w][lane][h] = p[h];
        ssrc[w][lane] = src;
        __syncwarp();
        int cnt = min(32, end - j0);
        #pragma unroll 8
        for (int t = 0; t < cnt; t++) {
            float pw = sp[w][t][hsel];
            den += pw;
            unsigned long long pw2;
            PACK2(pw2, pw, pw);
            ulonglong2 xv = ((const ulonglong2*)(X + (size_t)ssrc[w][t] * HID))[lane];
            FMA2(acc01, pw2, xv.x);
            FMA2(acc23, pw2, xv.y);
        }
        __syncwarp();
    }

    float inv = 1.f / (den + 1e-10f);
    float ax, ay, az, aw;
    UNPACK2(ax, ay, acc01);
    UNPACK2(az, aw, acc23);
    ((float4*)(g_agg + (size_t)node * HID))[lane] =
        make_float4(ax * inv, ay * inv, az * inv, aw * inv);
}

// ---- k5: out = agg @ out_w + out_b : 128x128 tile, 8x8 micro, f32x2 FMA ----
__global__ void k_gemm(const float* __restrict__ W,
                       const float* __restrict__ bias,
                       float* __restrict__ out, int n) {
    __shared__ float As[128][36];
    __shared__ float Bs[32][132];
    int tid = threadIdx.x;
    int tx = tid & 15;
    int ty = tid >> 4;
    int m0 = blockIdx.x * 128;

    unsigned long long acc2[8][4];
    #pragma unroll
    for (int i = 0; i < 8; i++)
        #pragma unroll
        for (int jp = 0; jp < 4; jp++) acc2[i][jp] = 0ULL;

    for (int kt = 0; kt < HID; kt += 32) {
        #pragma unroll
        for (int q = 0; q < 4; q++) {
            int id = q * 256 + tid;
            int row = id >> 3;
            int kq = (id & 7) * 4;
            float4 v = make_float4(0.f, 0.f, 0.f, 0.f);
            if (m0 + row < n)
                v = *(const float4*)(g_agg + (size_t)(m0 + row) * HID + kt + kq);
            *(float4*)&As[row][kq] = v;
        }
        #pragma unroll
        for (int q = 0; q < 4; q++) {
            int id = q * 256 + tid;
            int kk = id >> 5;
            int c4 = (id & 31) * 4;
            float4 v = *(const float4*)(W + (size_t)(kt + kk) * HID + c4);
            *(float4*)&Bs[kk][c4] = v;
        }
        __syncthreads();
        #pragma unroll
        for (int k = 0; k < 32; k++) {
            unsigned long long ad[8];
            #pragma unroll
            for (int i = 0; i < 8; i++) {
                float a = As[ty * 8 + i][k];
                PACK2(ad[i], a, a);
            }
            ulonglong2 b01 = *(const ulonglong2*)&Bs[k][tx * 8];
            ulonglong2 b23 = *(const ulonglong2*)&Bs[k][tx * 8 + 4];
            #pragma unroll
            for (int i = 0; i < 8; i++) {
                FMA2(acc2[i][0], ad[i], b01.x);
                FMA2(acc2[i][1], ad[i], b01.y);
                FMA2(acc2[i][2], ad[i], b23.x);
                FMA2(acc2[i][3], ad[i], b23.y);
            }
        }
        __syncthreads();
    }

    float b8[8];
    #pragma unroll
    for (int j = 0; j < 8; j++) b8[j] = bias[tx * 8 + j];

    #pragma unroll
    for (int i = 0; i < 8; i++) {
        int row = m0 + ty * 8 + i;
        if (row >= n) continue;
        float f0, f1, f2, f3, f4, f5, f6, f7;
        UNPACK2(f0, f1, acc2[i][0]);
        UNPACK2(f2, f3, acc2[i][1]);
        UNPACK2(f4, f5, acc2[i][2]);
        UNPACK2(f6, f7, acc2[i][3]);
        float* op = out + (size_t)row * HID + tx * 8;
        *(float4*)op       = make_float4(f0 + b8[0], f1 + b8[1], f2 + b8[2], f3 + b8[3]);
        *(float4*)(op + 4) = make_float4(f4 + b8[4], f5 + b8[5], f6 + b8[6], f7 + b8[7]);
    }
}

extern "C" void kernel_launch(void* const* d_in, const int* in_sizes, int n_in,
                              void* d_out, int out_size) {
    const float* X      = (const float*)d_in[0];
    const int*   ei     = (const int*)d_in[1];
    const float* node_w = (const float*)d_in[2];
    const float* node_b = (const float*)d_in[3];
    const float* att_w  = (const float*)d_in[4];
    const float* out_w  = (const float*)d_in[5];
    const float* out_b  = (const float*)d_in[6];
    float*       out    = (float*)d_out;

    int n = in_sizes[0] / HID;
    int e = in_sizes[1] / 2;
    int nb = (n + SCAN_B - 1) / SCAN_B;
    int na = (n + 7) / 8;

    k_count     <<<(e + 1023) / 1024, 256>>>(ei, e, n, node_w, node_b, att_w);
    k_alpha_scan<<<nb + na, 256>>>(X, n, nb);
    k_scatter   <<<(e + 1023) / 1024, 256>>>(ei, e, n);
    k_agg       <<<na, 256>>>(X, n);
    k_gemm      <<<(n + 127) / 128, 256>>>(out_w, out_b, out, n);
}

// round 11
// speedup vs baseline: 1.0117x; 1.0117x over previous
#include <cuda_runtime.h>

#define HID 128
#define H   8
#define HD  16
#define NMAX 50000
#define EMAX 800000
#define SCAN_B 256

// packed f32x2 helpers (sm_100a)
#define PACK2(out, lo, hi) \
    asm("mov.b64 %0, {%1, %2};" : "=l"(out) : "r"(__float_as_uint(lo)), "r"(__float_as_uint(hi)))
#define UNPACK2(lo, hi, in) \
    { unsigned int _l, _h; \
      asm("mov.b64 {%0, %1}, %2;" : "=r"(_l), "=r"(_h) : "l"(in)); \
      lo = __uint_as_float(_l); hi = __uint_as_float(_h); }
#define FMA2(d, a, b) \
    asm("fma.rn.f32x2 %0, %1, %2, %0;" : "+l"(d) : "l"(a), "l"(b))

// ---------------- scratch (no allocations; statics are zero-initialized) ----------------
__device__ float g_weff_src[HID * H];
__device__ float g_weff_dst[HID * H];
__device__ float g_beff[2 * H];
__device__ float g_alpha_src[NMAX * H];
__device__ float g_alpha_dst[NMAX * H];
__device__ int   g_count[NMAX];          // zero at load; re-zeroed by k_scatter each call
__device__ int   g_offsets[NMAX + 1];
__device__ int   g_rank[EMAX];           // edge's arrival index within its dst segment
__device__ int   g_src_sorted[EMAX];
__device__ float g_agg[NMAX * HID];

// ---- k1: degree histogram (+rank capture), x4 vectorized + (block 0) weff fold ----
__global__ void k_count(const int* __restrict__ ei, int e, int n,
                        const float* __restrict__ node_w,
                        const float* __restrict__ node_b,
                        const float* __restrict__ att_w) {
    int idx = blockIdx.x * blockDim.x + threadIdx.x;
    int base = idx * 4;
    if (base + 3 < e) {
        int4 c4 = *(const int4*)(ei + e + base);
        int r0, r1, r2, r3;
        r0 = atomicAdd(&g_count[min(max(c4.x, 0), n - 1)], 1);
        r1 = atomicAdd(&g_count[min(max(c4.y, 0), n - 1)], 1);
        r2 = atomicAdd(&g_count[min(max(c4.z, 0), n - 1)], 1);
        r3 = atomicAdd(&g_count[min(max(c4.w, 0), n - 1)], 1);
        *(int4*)(g_rank + base) = make_int4(r0, r1, r2, r3);
    } else {
        for (int i = base; i < e; i++) {
            int c = min(max(ei[e + i], 0), n - 1);
            g_rank[i] = atomicAdd(&g_count[c], 1);
        }
    }
    if (blockIdx.x == 0) {
        int t = threadIdx.x;
        for (int p = t; p < HID * H; p += blockDim.x) {
            int k = p / H, h = p % H;
            float ss = 0.f, sd = 0.f;
            #pragma unroll
            for (int d = 0; d < HD; d++) {
                ss += node_w[k * (2 * HID) + h * (2 * HD) + d]      * att_w[h * (2 * HD) + d];
                sd += node_w[k * (2 * HID) + h * (2 * HD) + HD + d] * att_w[h * (2 * HD) + HD + d];
            }
            g_weff_src[k * H + h] = ss;
            g_weff_dst[k * H + h] = sd;
        }
        if (t < H) {
            float bs = 0.f, bd = 0.f;
            #pragma unroll
            for (int d = 0; d < HD; d++) {
                bs += node_b[t * (2 * HD) + d]      * att_w[t * (2 * HD) + d];
                bd += node_b[t * (2 * HD) + HD + d] * att_w[t * (2 * HD) + HD + d];
            }
            g_beff[t]     = bs;
            g_beff[H + t] = bd;
        }
    }
}

// ---- k2: blocks [0,nb): offsets scan (self-summed prefix); blocks [nb,..): alpha ----
__global__ void k_alpha_scan(const float* __restrict__ X, int n, int nb) {
    __shared__ float sw[16][HID];
    __shared__ int wsum[8];
    __shared__ int s_base;
    int tid = threadIdx.x, lane = tid & 31, wid = tid >> 5;

    if (blockIdx.x < nb) {
        int pend = blockIdx.x * SCAN_B;
        int sum = 0;
        for (int i = tid; i < pend; i += SCAN_B) sum += g_count[i];
        #pragma unroll
        for (int o = 16; o > 0; o >>= 1) sum += __shfl_xor_sync(0xffffffffu, sum, o);
        if (lane == 0) wsum[wid] = sum;
        __syncthreads();
        if (tid == 0) {
            int s = 0;
            #pragma unroll
            for (int k = 0; k < 8; k++) s += wsum[k];
            s_base = s;
        }
        __syncthreads();
        int bbase = s_base;
        __syncthreads();

        int i = pend + tid;
        int v = (i < n) ? g_count[i] : 0;
        int x = v;
        #pragma unroll
        for (int o = 1; o < 32; o <<= 1) {
            int y = __shfl_up_sync(0xffffffffu, x, o);
            if (lane >= o) x += y;
        }
        if (lane == 31) wsum[wid] = x;
        __syncthreads();
        if (wid == 0 && lane < 8) {
            int s = wsum[lane];
            #pragma unroll
            for (int o = 1; o < 8; o <<= 1) {
                int y = __shfl_up_sync(0xffu, s, o);
                if (lane >= o) s += y;
            }
            wsum[lane] = s;
        }
        __syncthreads();
        int woff = (wid > 0) ? wsum[wid - 1] : 0;
        int incl = bbase + woff + x;
        if (i < n) g_offsets[i] = incl - v;
        if (blockIdx.x == nb - 1 && tid == SCAN_B - 1) g_offsets[n] = incl;
        return;
    }

    for (int idx = tid; idx < 16 * HID; idx += blockDim.x) {
        int hh = idx >> 7, k = idx & 127;
        sw[hh][k] = (hh < 8) ? g_weff_src[k * H + hh] : g_weff_dst[k * H + (hh - 8)];
    }
    __syncthreads();
    int node = (blockIdx.x - nb) * 8 + wid;
    if (node >= n) return;
    float4 xv = ((const float4*)(X + (size_t)node * HID))[lane];
    float r[16];
    #pragma unroll
    for (int hh = 0; hh < 16; hh++) {
        float4 wv = *(const float4*)&sw[hh][lane * 4];
        r[hh] = xv.x * wv.x + xv.y * wv.y + xv.z * wv.z + xv.w * wv.w;
    }
    #pragma unroll
    for (int o = 16; o > 0; o >>= 1)
        #pragma unroll
        for (int hh = 0; hh < 16; hh++)
            r[hh] += __shfl_xor_sync(0xffffffffu, r[hh], o);
    if (lane == 0) {
        float4* ps = (float4*)(g_alpha_src + (size_t)node * H);
        ps[0] = make_float4(r[0] + g_beff[0], r[1] + g_beff[1], r[2] + g_beff[2], r[3] + g_beff[3]);
        ps[1] = make_float4(r[4] + g_beff[4], r[5] + g_beff[5], r[6] + g_beff[6], r[7] + g_beff[7]);
        float4* pd = (float4*)(g_alpha_dst + (size_t)node * H);
        pd[0] = make_float4(r[8]  + g_beff[8],  r[9]  + g_beff[9],  r[10] + g_beff[10], r[11] + g_beff[11]);
        pd[1] = make_float4(r[12] + g_beff[12], r[13] + g_beff[13], r[14] + g_beff[14], r[15] + g_beff[15]);
    }
}

// ---- k3: atomic-free permutation scatter, x4 vectorized; also zeroes g_count ----
__global__ void k_scatter(const int* __restrict__ ei, int e, int n) {
    int idx = blockIdx.x * blockDim.x + threadIdx.x;
    if (idx < n) g_count[idx] = 0;
    int base = idx * 4;
    if (base + 3 < e) {
        int4 r4 = *(const int4*)(ei + base);
        int4 c4 = *(const int4*)(ei + e + base);
        int4 k4 = *(const int4*)(g_rank + base);
        int o0 = g_offsets[min(max(c4.x, 0), n - 1)];
        int o1 = g_offsets[min(max(c4.y, 0), n - 1)];
        int o2 = g_offsets[min(max(c4.z, 0), n - 1)];
        int o3 = g_offsets[min(max(c4.w, 0), n - 1)];
        g_src_sorted[o0 + k4.x] = min(max(r4.x, 0), n - 1);
        g_src_sorted[o1 + k4.y] = min(max(r4.y, 0), n - 1);
        g_src_sorted[o2 + k4.z] = min(max(r4.z, 0), n - 1);
        g_src_sorted[o3 + k4.w] = min(max(r4.w, 0), n - 1);
    } else {
        for (int i = base; i < e; i++) {
            int row = min(max(ei[i], 0), n - 1);
            int col = min(max(ei[e + i], 0), n - 1);
            g_src_sorted[g_offsets[col] + g_rank[i]] = row;
        }
    }
}

// ---- k4: fused scores + softmax + gather; transposed staging, quad-unrolled ----
__global__ void __launch_bounds__(256) k_agg(const float* __restrict__ X, int n) {
    __shared__ __align__(16) float sp2[8][8][36];   // [warp][head][edge+pad4]
    __shared__ __align__(16) int   ssrc[8][32];
    int w = threadIdx.x >> 5, lane = threadIdx.x & 31;
    int node = blockIdx.x * 8 + w;
    if (node >= n) return;
    int start = g_offsets[node];
    int end   = g_offsets[node + 1];

    const float4* bd4 = (const float4*)(g_alpha_dst + (size_t)node * H);
    float4 bd0 = bd4[0], bd1 = bd4[1];

    float den = 0.f;
    unsigned long long accA0 = 0ULL, accA1 = 0ULL, accB0 = 0ULL, accB1 = 0ULL;
    const int hsel = lane >> 2;
    float (*spw)[36] = sp2[w];
    int*   srcw      = ssrc[w];

    for (int j0 = start; j0 < end; j0 += 32) {
        int j = j0 + lane;
        float p[8];
        int src = 0;
        if (j < end) {
            src = g_src_sorted[j];
            const float4* as4 = (const float4*)(g_alpha_src + (size_t)src * H);
            float4 a0 = as4[0], a1 = as4[1];
            float s[8];
            s[0] = a0.x + bd0.x; s[1] = a0.y + bd0.y;
            s[2] = a0.z + bd0.z; s[3] = a0.w + bd0.w;
            s[4] = a1.x + bd1.x; s[5] = a1.y + bd1.y;
            s[6] = a1.z + bd1.z; s[7] = a1.w + bd1.w;
            #pragma unroll
            for (int h = 0; h < 8; h++) {
                float v = (s[h] >= 0.f) ? s[h] : 0.2f * s[h];
                p[h] = __expf(v);
            }
        } else {
            #pragma unroll
            for (int h = 0; h < 8; h++) p[h] = 0.f;
        }
        #pragma unroll
        for (int h = 0; h < 8; h++) spw[h][lane] = p[h];   // transposed store
        srcw[lane] = src;
        __syncwarp();

        int cnt = min(32, end - j0);
        int t0 = 0;
        for (; t0 + 4 <= cnt; t0 += 4) {
            int4   s4  = *(const int4*)(srcw + t0);             // broadcast LDS.128
            float4 pw4 = *(const float4*)(&spw[hsel][t0]);      // conflict-free LDS.128
            ulonglong2 x0 = ((const ulonglong2*)(X + (size_t)s4.x * HID))[lane];
            ulonglong2 x1 = ((const ulonglong2*)(X + (size_t)s4.y * HID))[lane];
            ulonglong2 x2 = ((const ulonglong2*)(X + (size_t)s4.z * HID))[lane];
            ulonglong2 x3 = ((const ulonglong2*)(X + (size_t)s4.w * HID))[lane];
            unsigned long long q0, q1, q2, q3;
            PACK2(q0, pw4.x, pw4.x); PACK2(q1, pw4.y, pw4.y);
            PACK2(q2, pw4.z, pw4.z); PACK2(q3, pw4.w, pw4.w);
            FMA2(accA0, q0, x0.x); FMA2(accA1, q0, x0.y);
            FMA2(accB0, q1, x1.x); FMA2(accB1, q1, x1.y);
            FMA2(accA0, q2, x2.x); FMA2(accA1, q2, x2.y);
            FMA2(accB0, q3, x3.x); FMA2(accB1, q3, x3.y);
            den += (pw4.x + pw4.y) + (pw4.z + pw4.w);
        }
        for (; t0 < cnt; t0++) {
            int   s  = srcw[t0];
            float pw = spw[hsel][t0];
            ulonglong2 xv = ((const ulonglong2*)(X + (size_t)s * HID))[lane];
            unsigned long long q;
            PACK2(q, pw, pw);
            FMA2(accA0, q, xv.x);
            FMA2(accA1, q, xv.y);
            den += pw;
        }
        __syncwarp();
    }

    float a0x, a0y, a1x, a1y, b0x, b0y, b1x, b1y;
    UNPACK2(a0x, a0y, accA0); UNPACK2(b0x, b0y, accB0);
    UNPACK2(a1x, a1y, accA1); UNPACK2(b1x, b1y, accB1);
    float inv = 1.f / (den + 1e-10f);
    ((float4*)(g_agg + (size_t)node * HID))[lane] =
        make_float4((a0x + b0x) * inv, (a0y + b0y) * inv,
                    (a1x + b1x) * inv, (a1y + b1y) * inv);
}

// ---- k5: out = agg @ out_w + out_b : 128x128 tile, 8x8 micro, f32x2 FMA ----
__global__ void k_gemm(const float* __restrict__ W,
                       const float* __restrict__ bias,
                       float* __restrict__ out, int n) {
    __shared__ float As[128][36];
    __shared__ float Bs[32][132];
    int tid = threadIdx.x;
    int tx = tid & 15;
    int ty = tid >> 4;
    int m0 = blockIdx.x * 128;

    unsigned long long acc2[8][4];
    #pragma unroll
    for (int i = 0; i < 8; i++)
        #pragma unroll
        for (int jp = 0; jp < 4; jp++) acc2[i][jp] = 0ULL;

    for (int kt = 0; kt < HID; kt += 32) {
        #pragma unroll
        for (int q = 0; q < 4; q++) {
            int id = q * 256 + tid;
            int row = id >> 3;
            int kq = (id & 7) * 4;
            float4 v = make_float4(0.f, 0.f, 0.f, 0.f);
            if (m0 + row < n)
                v = *(const float4*)(g_agg + (size_t)(m0 + row) * HID + kt + kq);
            *(float4*)&As[row][kq] = v;
        }
        #pragma unroll
        for (int q = 0; q < 4; q++) {
            int id = q * 256 + tid;
            int kk = id >> 5;
            int c4 = (id & 31) * 4;
            float4 v = *(const float4*)(W + (size_t)(kt + kk) * HID + c4);
            *(float4*)&Bs[kk][c4] = v;
        }
        __syncthreads();
        #pragma unroll
        for (int k = 0; k < 32; k++) {
            unsigned long long ad[8];
            #pragma unroll
            for (int i = 0; i < 8; i++) {
                float a = As[ty * 8 + i][k];
                PACK2(ad[i], a, a);
            }
            ulonglong2 b01 = *(const ulonglong2*)&Bs[k][tx * 8];
            ulonglong2 b23 = *(const ulonglong2*)&Bs[k][tx * 8 + 4];
            #pragma unroll
            for (int i = 0; i < 8; i++) {
                FMA2(acc2[i][0], ad[i], b01.x);
                FMA2(acc2[i][1], ad[i], b01.y);
                FMA2(acc2[i][2], ad[i], b23.x);
                FMA2(acc2[i][3], ad[i], b23.y);
            }
        }
        __syncthreads();
    }

    float b8[8];
    #pragma unroll
    for (int j = 0; j < 8; j++) b8[j] = bias[tx * 8 + j];

    #pragma unroll
    for (int i = 0; i < 8; i++) {
        int row = m0 + ty * 8 + i;
        if (row >= n) continue;
        float f0, f1, f2, f3, f4, f5, f6, f7;
        UNPACK2(f0, f1, acc2[i][0]);
        UNPACK2(f2, f3, acc2[i][1]);
        UNPACK2(f4, f5, acc2[i][2]);
        UNPACK2(f6, f7, acc2[i][3]);
        float* op = out + (size_t)row * HID + tx * 8;
        *(float4*)op       = make_float4(f0 + b8[0], f1 + b8[1], f2 + b8[2], f3 + b8[3]);
        *(float4*)(op + 4) = make_float4(f4 + b8[4], f5 + b8[5], f6 + b8[6], f7 + b8[7]);
    }
}

extern "C" void kernel_launch(void* const* d_in, const int* in_sizes, int n_in,
                              void* d_out, int out_size) {
    const float* X      = (const float*)d_in[0];
    const int*   ei     = (const int*)d_in[1];
    const float* node_w = (const float*)d_in[2];
    const float* node_b = (const float*)d_in[3];
    const float* att_w  = (const float*)d_in[4];
    const float* out_w  = (const float*)d_in[5];
    const float* out_b  = (const float*)d_in[6];
    float*       out    = (float*)d_out;

    int n = in_sizes[0] / HID;
    int e = in_sizes[1] / 2;
    int nb = (n + SCAN_B - 1) / SCAN_B;
    int na = (n + 7) / 8;

    k_count     <<<(e + 1023) / 1024, 256>>>(ei, e, n, node_w, node_b, att_w);
    k_alpha_scan<<<nb + na, 256>>>(X, n, nb);
    k_scatter   <<<(e + 1023) / 1024, 256>>>(ei, e, n);
    k_agg       <<<na, 256>>>(X, n);
    k_gemm      <<<(n + 127) / 128, 256>>>(out_w, out_b, out, n);
}